// round 17
// baseline (speedup 1.0000x reference)
#include <cuda_runtime.h>
#include <cuda_fp16.h>
#include <cstdint>

#define BATCH 8192
#define NREF  2048
#define KDIM  256
#define MT    128             // M rows per mtile (4 warps x 32 rows)
#define NM    64              // mtiles
#define NPACK 1024            // packed columns total (2 refs each)
#define NT    64              // packed cols per tile (chunk)
#define NCH   16              // chunks per mtile (NPACK/NT)
#define NITEMS 1024           // 64 mtiles x 16 chunks, mtile-major
#define NSM   148
#define GRID  296             // 2 CTAs per SM, single wave
#define TILE_B 32768          // bytes per B tile (64 cols x 512 B)

// g_B: fragment-order layout. Per chunk T (0..15):
//   [grp(2)][ksp(8)][u(4)][lane(32)] -> uint4 {b0,b1 @ks=2ksp, b0,b1 @ks=2ksp+1}
__device__ uint4 g_B[NPACK * KDIM / 8];    // 1 MB
__device__ float g_cc[NPACK];              // cntR[2n] + 1024*cntR[2n+1]

struct Smem {
    uint4 B[2][TILE_B / 16];  // 2 x 32768 B
    float cc[NPACK];          // all 1024 cc values (4096 B)
};
#define SMEM_SZ (int)sizeof(Smem)

// ---------------------------------------------------------------------------
__device__ __forceinline__ uint32_t s2u(const void* p) {
    uint32_t a;
    asm("{ .reg .u64 t; cvta.to.shared.u64 t, %1; cvt.u32.u64 %0, t; }" : "=r"(a) : "l"(p));
    return a;
}
__device__ __forceinline__ void cpa16(uint32_t dst, const void* src) {
    asm volatile("cp.async.cg.shared.global [%0], [%1], 16;" :: "r"(dst), "l"(src));
}
template <int N>
__device__ __forceinline__ void cpwait() {
    asm volatile("cp.async.wait_group %0;" :: "n"(N) : "memory");
}
__device__ __forceinline__ void mma_f16f32(float* c, const uint32_t* a,
                                           uint32_t b0, uint32_t b1) {
    asm volatile(
        "mma.sync.aligned.m16n8k16.row.col.f32.f16.f16.f32 "
        "{%0,%1,%2,%3},{%4,%5,%6,%7},{%8,%9},{%0,%1,%2,%3};"
        : "+f"(c[0]), "+f"(c[1]), "+f"(c[2]), "+f"(c[3])
        : "r"(a[0]), "r"(a[1]), "r"(a[2]), "r"(a[3]), "r"(b0), "r"(b1));
}
__device__ __forceinline__ uint32_t packh2(float x, float y) {
    __half2 h = __floats2half2_rn(x, y);
    return *reinterpret_cast<uint32_t*>(&h);
}
// decode packed distance: comb = d0 + 1024*d1, d0,d1 in [0,256] (exact)
__device__ __forceinline__ void decode_min(float acc, float ccv, float& rmin) {
    float comb = acc + ccv;
    float d1 = rintf(comb * (1.0f / 1024.0f));     // d0/1024 <= 0.25 -> no ties
    float d0 = fmaf(d1, -1024.0f, comb);           // exact
    rmin = fminf(rmin, fminf(d0, d1));
}

// ---------------------------------------------------------------------------
// Kernel 1 (prep): out init; fragment-order radix-1024 B pack; cc. (= R15)
//   val(n,k) = 1025 - 2*R[2n][k] - 2048*R[2n+1][k]  in {+-1023,+-1025} (exact)
// ---------------------------------------------------------------------------
__global__ void prep_kernel(const float* __restrict__ R, int* __restrict__ outi) {
    int i = blockIdx.x * 256 + threadIdx.x;      // 65536 threads

    if (i < BATCH) outi[i] = 0x7f800000;         // +inf bits

    if (i < 32768) {
        // one uint4 of fragment-order B per thread
        int T    = i >> 11;                      // chunk 0..15
        int r    = i & 2047;
        int grp  = r >> 10;
        int ksp  = (r >> 7) & 7;
        int u    = (r >> 5) & 3;
        int lane = r & 31;
        int g    = lane >> 2, q = lane & 3;
        int n    = T * NT + (grp * 4 + u) * 8 + g;   // packed col
        int kk0  = ksp * 32 + q * 4;

        const float* r0 = R + (size_t)(2 * n) * KDIM;
        const float* r1 = r0 + KDIM;
        float4 a0 = *reinterpret_cast<const float4*>(r0 + kk0);
        float4 a1 = *reinterpret_cast<const float4*>(r0 + kk0 + 16);
        float4 b0 = *reinterpret_cast<const float4*>(r1 + kk0);
        float4 b1 = *reinterpret_cast<const float4*>(r1 + kk0 + 16);

        uint4 o;
        o.x = packh2(1025.f - 2.f * a0.x - 2048.f * b0.x,
                     1025.f - 2.f * a0.y - 2048.f * b0.y);
        o.y = packh2(1025.f - 2.f * a0.z - 2048.f * b0.z,
                     1025.f - 2.f * a0.w - 2048.f * b0.w);
        o.z = packh2(1025.f - 2.f * a1.x - 2048.f * b1.x,
                     1025.f - 2.f * a1.y - 2048.f * b1.y);
        o.w = packh2(1025.f - 2.f * a1.z - 2048.f * b1.z,
                     1025.f - 2.f * a1.w - 2048.f * b1.w);
        g_B[i] = o;
    } else {
        // cc: one warp per packed col (1024 warps)
        int t = i - 32768;
        int n = t >> 5, lane = t & 31;
        const float* r0 = R + (size_t)(2 * n) * KDIM;
        float s0 = 0.f, s1 = 0.f;
        #pragma unroll
        for (int k = lane; k < KDIM; k += 32) {
            s0 += r0[k];
            s1 += r0[KDIM + k];
        }
        float s = s0 + 1024.f * s1;
        #pragma unroll
        for (int o = 16; o; o >>= 1) s += __shfl_xor_sync(0xffffffffu, s, o);
        if (lane == 0) g_cc[n] = s;
    }
}

// ---------------------------------------------------------------------------
// Kernel 2 (main): SM-aware balanced partition. bid -> smid = LUT[bid % 148],
// so CTAs b and b+148 share an SM: SM s owns items [1024s/148, 1024(s+1)/148),
// split ceil/floor between its two CTAs -> per-SM makespan 7 tiles (was 8).
// ---------------------------------------------------------------------------
__device__ __forceinline__ void load_B(Smem& sm, int item, int buf, int tid) {
    int chunk = item & (NCH - 1);
    const char* src = (const char*)g_B + (size_t)chunk * TILE_B;
    uint32_t dst = s2u(&sm.B[buf][0]);
    #pragma unroll
    for (int j = 0; j < 16; j++) {               // 2048 x 16B / 128 threads
        int i = tid + j * 128;
        cpa16(dst + i * 16, src + (size_t)i * 16);
    }
    asm volatile("cp.async.commit_group;" ::: "memory");
}

__global__ void __launch_bounds__(128, 2) hamming_sm(const float* __restrict__ S,
                                                     int* __restrict__ outi) {
    extern __shared__ __align__(16) char smraw[];
    Smem& sm = *reinterpret_cast<Smem*>(smraw);

    const int tid  = threadIdx.x;
    const int wid  = tid >> 5;
    const int lane = tid & 31;
    const int g    = lane >> 2;
    const int q    = lane & 3;

    // SM-aware range: pair (b, b+148) co-resident; split SM range ceil/floor
    const int smid = blockIdx.x % NSM;
    const int half = blockIdx.x / NSM;
    const int s0 = (smid * NITEMS) / NSM;
    const int s1 = ((smid + 1) * NITEMS) / NSM;
    const int mid = s0 + ((s1 - s0 + 1) >> 1);
    const int start = half ? mid : s0;
    const int end   = half ? s1 : mid;

    int cur_m = start >> 4;

    load_B(sm, start, 0, tid);                   // first tile in flight

    // all 1024 cc values into smem
    for (int i = tid; i < NPACK / 4; i += 128)
        *reinterpret_cast<float4*>(&sm.cc[i * 4]) =
            *reinterpret_cast<const float4*>(&g_cc[i * 4]);

    // A fragments: 2 m16-tiles x 16 ks x 4 regs, contiguous float4 loads
    uint32_t a[2][16][4];
    auto loadA = [&](int m) {
        #pragma unroll
        for (int mt = 0; mt < 2; mt++) {
            const float* rowLo = S + ((size_t)(m * MT + wid * 32 + mt * 16 + g)) * KDIM;
            const float* rowHi = rowLo + 8 * KDIM;
            #pragma unroll
            for (int ks = 0; ks < 16; ks++) {
                float4 v0 = *reinterpret_cast<const float4*>(rowLo + ks * 16 + q * 4);
                float4 v1 = *reinterpret_cast<const float4*>(rowHi + ks * 16 + q * 4);
                a[mt][ks][0] = packh2(v0.x, v0.y);
                a[mt][ks][2] = packh2(v0.z, v0.w);
                a[mt][ks][1] = packh2(v1.x, v1.y);
                a[mt][ks][3] = packh2(v1.z, v1.w);
            }
        }
    };
    loadA(cur_m);

    float rmin[2][2] = {{__int_as_float(0x7f800000), __int_as_float(0x7f800000)},
                        {__int_as_float(0x7f800000), __int_as_float(0x7f800000)}};

    auto flush = [&](int m) {
        #pragma unroll
        for (int mt = 0; mt < 2; mt++)
            #pragma unroll
            for (int h = 0; h < 2; h++) {
                float v = rmin[mt][h];
                v = fminf(v, __shfl_xor_sync(0xffffffffu, v, 1));
                v = fminf(v, __shfl_xor_sync(0xffffffffu, v, 2));
                if (q == 0)
                    atomicMin(&outi[m * MT + wid * 32 + mt * 16 + h * 8 + g],
                              __float_as_int(v));
                rmin[mt][h] = __int_as_float(0x7f800000);
            }
    };

    int buf = 0;
    for (int it = start; it < end; it++) {
        if (it + 1 < end) {
            load_B(sm, it + 1, buf ^ 1, tid);
            cpwait<1>();
        } else {
            cpwait<0>();
        }
        __syncthreads();

        const uint4* Bb = sm.B[buf];
        const int ccT = (it & (NCH - 1)) * NT;

        #pragma unroll
        for (int grp = 0; grp < 2; grp++) {
            float c[2][4][4];
            #pragma unroll
            for (int mt = 0; mt < 2; mt++)
                #pragma unroll
                for (int u = 0; u < 4; u++)
                    c[mt][u][0] = c[mt][u][1] = c[mt][u][2] = c[mt][u][3] = 0.f;

            #pragma unroll
            for (int ksp = 0; ksp < 8; ksp++) {
                uint4 bw[4];
                #pragma unroll
                for (int u = 0; u < 4; u++)
                    bw[u] = Bb[((grp * 8 + ksp) * 4 + u) * 32 + lane];  // LDS.128

                #pragma unroll
                for (int u = 0; u < 4; u++) {
                    mma_f16f32(c[0][u], a[0][2 * ksp],     bw[u].x, bw[u].y);
                    mma_f16f32(c[1][u], a[1][2 * ksp],     bw[u].x, bw[u].y);
                    mma_f16f32(c[0][u], a[0][2 * ksp + 1], bw[u].z, bw[u].w);
                    mma_f16f32(c[1][u], a[1][2 * ksp + 1], bw[u].z, bw[u].w);
                }
            }

            // decode epilogue: acc column = 2 refs (comb = d0 + 1024*d1)
            #pragma unroll
            for (int u = 0; u < 4; u++) {
                int n0 = ccT + (grp * 4 + u) * 8 + q * 2;
                float2 ccv = *reinterpret_cast<const float2*>(&sm.cc[n0]);
                #pragma unroll
                for (int mt = 0; mt < 2; mt++) {
                    decode_min(c[mt][u][0], ccv.x, rmin[mt][0]);
                    decode_min(c[mt][u][1], ccv.y, rmin[mt][0]);
                    decode_min(c[mt][u][2], ccv.x, rmin[mt][1]);
                    decode_min(c[mt][u][3], ccv.y, rmin[mt][1]);
                }
            }
        }
        __syncthreads();          // done with sm.B[buf]; safe to refill

        if (it + 1 < end) {
            int nm = (it + 1) >> 4;
            if (nm != cur_m) { flush(cur_m); loadA(nm); cur_m = nm; }
        }
        buf ^= 1;
    }
    flush(cur_m);
}

// ---------------------------------------------------------------------------
extern "C" void kernel_launch(void* const* d_in, const int* in_sizes, int n_in,
                              void* d_out, int out_size) {
    const float* states = (const float*)d_in[0];
    const float* R      = (const float*)d_in[1];
    int* outi           = (int*)d_out;

    prep_kernel<<<256, 256>>>(R, outi);          // 65536 threads

    cudaFuncSetAttribute(hamming_sm, cudaFuncAttributeMaxDynamicSharedMemorySize, SMEM_SZ);
    hamming_sm<<<GRID, 128, SMEM_SZ>>>(states, outi);
}